// round 16
// baseline (speedup 1.0000x reference)
#include <cuda_runtime.h>
#include <cuda_bf16.h>

// Problem constants (fixed by the reference).
#define N_  512
#define L_  5
#define H_  8
#define D_  16
#define E_  10000

#define PAIRS_PER_BLK 256
#define THREADS_G     256
#define PP_           2
#define GRID_G        ((N_ * N_) / PAIRS_PER_BLK)          // 1024
#define NPROJ_BLOCKS  ((E_ + THREADS_G - 1) / THREADS_G)   // 40

// Scratch: projected edge table P[e][l][h] = dot(edge_features[e], W[1+l][h]).
// 400,000 floats = 1.6 MB (L2-resident). Chunk (e,l) = 32 B at byte offset
// e*160 + l*32; 160 ≡ 32 (mod 128) -> every chunk sits inside ONE 128B line.
__device__ float g_P[E_ * L_ * H_];

// Device-side dependency barrier state (reset by the last exiting block each
// launch -> deterministic across graph replays).
__device__ unsigned g_done = 0;   // projection blocks completed
__device__ unsigned g_exit = 0;   // blocks fully finished

// ---------------------------------------------------------------------------
// Single fused kernel.
// Phase A (blocks 0..39): projection, exact R7 per-thread shape (e = gtid).
// Phase B (all blocks):   stage indices -> wait for phase A -> R10 gather.
// ---------------------------------------------------------------------------
__global__ void __launch_bounds__(THREADS_G)
fused_kernel(const float* __restrict__ F,    // [E, D]
             const float* __restrict__ W,    // [L+1, H*D]
             const int*   __restrict__ spe,  // [N, N, L] int32
             float*       __restrict__ out)  // [H, N, N]
{
    __shared__ int   s_idx[PAIRS_PER_BLK * L_];        // 1280 ints
    __shared__ float s_out[H_ * (PAIRS_PER_BLK + 1)];  // padded stride

    const int b   = blockIdx.x;
    const int tid = threadIdx.x;
    const int base = b * PAIRS_PER_BLK;

    // ---- Phase B prologue: coalesced index staging (independent of g_P).
    // Runs on ALL blocks concurrently with phase A below on blocks 0..39.
    const int4* g4 = reinterpret_cast<const int4*>(spe + (size_t)base * L_);
    #pragma unroll
    for (int i = tid; i < (PAIRS_PER_BLK * L_) / 4; i += THREADS_G)
        reinterpret_cast<int4*>(s_idx)[i] = g4[i];

    // ---- Phase A: projection (blocks 0..39 only).
    if (b < NPROJ_BLOCKS) {
        int e = b * THREADS_G + tid;
        if (e < E_) {
            // W rows 1..L read straight from global: 3 KB, L2/L1-hot after
            // the first warp touches it; uniform per-warp addresses.
            const float4* fp = reinterpret_cast<const float4*>(F + (size_t)e * D_);
            float4 f0 = fp[0], f1 = fp[1], f2 = fp[2], f3 = fp[3];
            float fr[D_] = { f0.x, f0.y, f0.z, f0.w,
                             f1.x, f1.y, f1.z, f1.w,
                             f2.x, f2.y, f2.z, f2.w,
                             f3.x, f3.y, f3.z, f3.w };

            float pr[L_ * H_];
            #pragma unroll
            for (int l = 0; l < L_; ++l) {
                #pragma unroll
                for (int h = 0; h < H_; ++h) {
                    float acc = 0.0f;
                    const float* w = W + (1 + l) * (H_ * D_) + h * D_;
                    #pragma unroll
                    for (int d = 0; d < D_; ++d)
                        acc = fmaf(fr[d], __ldg(w + d), acc);
                    pr[l * H_ + h] = acc;
                }
            }

            float4* dst = reinterpret_cast<float4*>(g_P + (size_t)e * (L_ * H_));
            #pragma unroll
            for (int i = 0; i < (L_ * H_) / 4; ++i) {
                float4 v = { pr[4*i], pr[4*i+1], pr[4*i+2], pr[4*i+3] };
                dst[i] = v;
            }
        }
        __syncthreads();              // all P stores of this block issued
        __threadfence();              // release: make them device-visible
        if (tid == 0) atomicAdd(&g_done, 1u);
    }

    // ---- Wait for projection completion (acquire).
    if (tid == 0) {
        while (*(volatile unsigned*)&g_done < NPROJ_BLOCKS)
            __nanosleep(40);
        __threadfence();              // acquire: order g_P reads after flag
    }
    __syncthreads();                  // also closes the staging loop

    // ---- Phase B: gather/average, exact R10 shape (measured 10.8 us floor).
    const int pair = tid >> 1;        // 0..127
    const int c    = tid & 1;         // float4 chunk within the 32B row chunk
    const int coff = c * 4;

    float a[PP_][4];
    float cntf[PP_];
    #pragma unroll
    for (int pp = 0; pp < PP_; ++pp) {
        a[pp][0] = a[pp][1] = a[pp][2] = a[pp][3] = 0.f;
        cntf[pp] = 0.f;
    }

    #pragma unroll
    for (int pp = 0; pp < PP_; ++pp) {
        const int pr = pair + pp * 128;
        #pragma unroll
        for (int l = 0; l < L_; ++l) {
            int e = s_idx[pr * L_ + l];
            bool valid = (unsigned)e < (unsigned)E_;
            int  ei    = valid ? e : 0;
            float m    = valid ? 1.0f : 0.0f;
            const float4 v = *reinterpret_cast<const float4*>(
                g_P + (size_t)ei * (L_ * H_) + l * H_ + coff);
            a[pp][0] = fmaf(m, v.x, a[pp][0]);
            a[pp][1] = fmaf(m, v.y, a[pp][1]);
            a[pp][2] = fmaf(m, v.z, a[pp][2]);
            a[pp][3] = fmaf(m, v.w, a[pp][3]);
            cntf[pp] += m;
        }
    }

    #pragma unroll
    for (int pp = 0; pp < PP_; ++pp) {
        const int pr  = pair + pp * 128;
        float inv = 1.0f / fmaxf(cntf[pp], 1.0f);
        s_out[(coff + 0) * (PAIRS_PER_BLK + 1) + pr] = a[pp][0] * inv;
        s_out[(coff + 1) * (PAIRS_PER_BLK + 1) + pr] = a[pp][1] * inv;
        s_out[(coff + 2) * (PAIRS_PER_BLK + 1) + pr] = a[pp][2] * inv;
        s_out[(coff + 3) * (PAIRS_PER_BLK + 1) + pr] = a[pp][3] * inv;
    }
    __syncthreads();

    // 8 planes x 256 pairs, fully coalesced (1KB contiguous per plane seg).
    const int NN = N_ * N_;
    #pragma unroll
    for (int k = 0; k < (H_ * PAIRS_PER_BLK) / THREADS_G; ++k) {
        int i = k * THREADS_G + tid;
        int h = i >> 8;              // /256
        int j = i & 255;             // %256
        out[h * NN + base + j] = s_out[h * (PAIRS_PER_BLK + 1) + j];
    }

    // ---- Replay-safe reset: last block to finish zeroes the barrier state.
    __syncthreads();
    if (tid == 0) {
        unsigned done = atomicAdd(&g_exit, 1u);
        if (done == GRID_G - 1) {
            atomicExch(&g_done, 0u);
            atomicExch(&g_exit, 0u);
        }
    }
}

// ---------------------------------------------------------------------------
// Launch: inputs in metadata order:
//   d_in[0] = edge_features_s      float32 [E*D]
//   d_in[1] = edge_weights         float32 [(L+1)*H*D]
//   d_in[2] = shortest_path_edges  int32   [N*N*L]
// d_out = float32 [H*N*N]
//
// Single kernel: saves one graph-node launch + inter-kernel serialization.
// All 1024 blocks are wave-1 resident (32 regs, ~13 KB smem -> 8 blocks/SM
// x 148 SMs = 1184), so the device-side barrier cannot deadlock; projection
// blocks (0..39) are always scheduled first.
// ---------------------------------------------------------------------------
extern "C" void kernel_launch(void* const* d_in, const int* in_sizes, int n_in,
                              void* d_out, int out_size)
{
    const float* F   = (const float*)d_in[0];
    const float* W   = (const float*)d_in[1];
    const int*   spe = (const int*)d_in[2];
    float*       out = (float*)d_out;

    fused_kernel<<<GRID_G, THREADS_G>>>(F, W, spe, out);
}